// round 2
// baseline (speedup 1.0000x reference)
#include <cuda_runtime.h>
#include <cuda_bf16.h>
#include <cstdint>

// Problem constants
// B=2, S=4096, HS=4096, H=32, KV=8, D=128  -> M = B*S = 8192
#define M_TOK   8192
#define HS_DIM  4096
#define KVD_DIM 1024
#define N_HEADS 32
#define N_KV    8
#define HEAD_D  128

// Scratch (static __device__ arrays: allocation-free per harness rules)
__device__ float g_q [(size_t)M_TOK * HS_DIM];   // 134 MB
__device__ float g_k [(size_t)M_TOK * KVD_DIM];  //  33.5 MB
__device__ float g_v [(size_t)M_TOK * KVD_DIM];  //  33.5 MB
__device__ float g_ao[(size_t)M_TOK * HS_DIM];   // 134 MB

// ---------------------------------------------------------------------------
// SGEMM: C[M,N] = A[M,K] @ B[K,N], all row-major fp32.
// BM=BN=128, BK=8, 256 threads, each thread owns an 8x8 micro-tile split as
// 2x2 blocks of 4x4 at offsets {0,64} in each dim (conflict-free float4 LDS).
// Requires M%128==0, N%128==0, K%8==0 (true for all calls here).
// ---------------------------------------------------------------------------
__global__ __launch_bounds__(256, 2)
void sgemm_kernel(const float* __restrict__ A, const float* __restrict__ B,
                  float* __restrict__ C, int M, int N, int K)
{
    __shared__ float As[8][128];   // transposed A tile: As[k][m]
    __shared__ float Bs[8][128];   // Bs[k][n]

    const int tid  = threadIdx.x;
    const int brow = blockIdx.y;   // tile row  (M/128)
    const int bcol = blockIdx.x;   // tile col  (N/128)

    // A tile loads: 128 rows x 8 cols. thread -> (row = tid/2, col4 = (tid&1)*4)
    const int aRow = tid >> 1;
    const int aCol = (tid & 1) * 4;
    // B tile loads: 8 rows x 128 cols. thread -> (row = tid/32, col4 = (tid&31)*4)
    const int bRow = tid >> 5;
    const int bCol = (tid & 31) * 4;

    const float* Ap = A + (size_t)(brow * 128) * K;
    const float* Bp = B + (size_t)(bcol * 128);

    const int ty = tid >> 4;   // 0..15
    const int tx = tid & 15;   // 0..15

    float acc[8][8];
    #pragma unroll
    for (int i = 0; i < 8; i++)
        #pragma unroll
        for (int j = 0; j < 8; j++) acc[i][j] = 0.f;

    for (int k0 = 0; k0 < K; k0 += 8) {
        // load A tile (transposed into shared)
        float4 a4 = *(const float4*)(Ap + (size_t)aRow * K + k0 + aCol);
        As[aCol + 0][aRow] = a4.x;
        As[aCol + 1][aRow] = a4.y;
        As[aCol + 2][aRow] = a4.z;
        As[aCol + 3][aRow] = a4.w;
        // load B tile
        float4 b4 = *(const float4*)(Bp + (size_t)(k0 + bRow) * N + bCol);
        *(float4*)&Bs[bRow][bCol] = b4;
        __syncthreads();

        #pragma unroll
        for (int kk = 0; kk < 8; kk++) {
            float4 m0 = *(const float4*)&As[kk][ty * 4];
            float4 m1 = *(const float4*)&As[kk][64 + ty * 4];
            float4 n0 = *(const float4*)&Bs[kk][tx * 4];
            float4 n1 = *(const float4*)&Bs[kk][64 + tx * 4];
            float rm[8] = {m0.x, m0.y, m0.z, m0.w, m1.x, m1.y, m1.z, m1.w};
            float rn[8] = {n0.x, n0.y, n0.z, n0.w, n1.x, n1.y, n1.z, n1.w};
            #pragma unroll
            for (int i = 0; i < 8; i++)
                #pragma unroll
                for (int j = 0; j < 8; j++)
                    acc[i][j] += rm[i] * rn[j];
        }
        __syncthreads();
    }

    // Write back: rows (im*64 + ty*4 + ii), cols (jn*64 + tx*4 ..+3)
    #pragma unroll
    for (int im = 0; im < 2; im++) {
        #pragma unroll
        for (int ii = 0; ii < 4; ii++) {
            int row = brow * 128 + im * 64 + ty * 4 + ii;
            float* Crow = C + (size_t)row * N + bcol * 128;
            int i = im * 4 + ii;
            float4 c0 = {acc[i][0], acc[i][1], acc[i][2], acc[i][3]};
            float4 c1 = {acc[i][4], acc[i][5], acc[i][6], acc[i][7]};
            *(float4*)(Crow + tx * 4)      = c0;
            *(float4*)(Crow + 64 + tx * 4) = c1;
        }
    }
}

// ---------------------------------------------------------------------------
// Per-token "attention": for each token, 32 q-heads attend over the 8 kv
// heads (GQA repeat + softmax multiplicity cancels algebraically; RoPE is a
// same-position rotation and cancels exactly in q·k, v is un-roped).
//   s[h][g]  = q[h]·k[g] / sqrt(128)
//   w[h][:]  = softmax_g(s[h][:])
//   ao[h][d] = sum_g w[h][g] * v[g][d]
// One block per token, 128 threads.
// ---------------------------------------------------------------------------
__global__ __launch_bounds__(128)
void attn_kernel(const float* __restrict__ q, const float* __restrict__ k,
                 const float* __restrict__ v, float* __restrict__ ao)
{
    const int tok = blockIdx.x;
    const int tid = threadIdx.x;

    __shared__ float qs[N_HEADS][132];  // pad 128->132 to dodge bank conflicts
    __shared__ float ks[N_KV][132];
    __shared__ float vs[N_KV][132];
    __shared__ float sc[N_HEADS][8];
    __shared__ float w [N_HEADS][8];

    const float* qg = q + (size_t)tok * HS_DIM;
    const float* kg = k + (size_t)tok * KVD_DIM;
    const float* vg = v + (size_t)tok * KVD_DIM;

    // cooperative loads (float4)
    for (int i = tid; i < HS_DIM / 4; i += 128) {
        float4 t4 = *(const float4*)(qg + i * 4);
        int h = (i * 4) >> 7, d = (i * 4) & 127;
        *(float4*)&qs[h][d] = t4;
    }
    for (int i = tid; i < KVD_DIM / 4; i += 128) {
        float4 t4 = *(const float4*)(kg + i * 4);
        int g = (i * 4) >> 7, d = (i * 4) & 127;
        *(float4*)&ks[g][d] = t4;
    }
    for (int i = tid; i < KVD_DIM / 4; i += 128) {
        float4 t4 = *(const float4*)(vg + i * 4);
        int g = (i * 4) >> 7, d = (i * 4) & 127;
        *(float4*)&vs[g][d] = t4;
    }
    __syncthreads();

    // 256 dot products of length 128 -> 2 per thread
    const float scale = 0.088388347648318447f;  // 1/sqrt(128)
    #pragma unroll
    for (int r = 0; r < 2; r++) {
        int sid = r * 128 + tid;
        int h = sid >> 3, g = sid & 7;
        float a = 0.f;
        #pragma unroll 8
        for (int d = 0; d < HEAD_D; d++) a += qs[h][d] * ks[g][d];
        sc[h][g] = a * scale;
    }
    __syncthreads();

    // softmax over the 8 kv heads, one thread per q-head
    if (tid < N_HEADS) {
        float m = sc[tid][0];
        #pragma unroll
        for (int g = 1; g < 8; g++) m = fmaxf(m, sc[tid][g]);
        float e[8], s = 0.f;
        #pragma unroll
        for (int g = 0; g < 8; g++) { e[g] = __expf(sc[tid][g] - m); s += e[g]; }
        float inv = 1.f / s;
        #pragma unroll
        for (int g = 0; g < 8; g++) w[tid][g] = e[g] * inv;
    }
    __syncthreads();

    // mix: thread tid owns dim d=tid for all 32 heads; v cached in regs
    float vr[8];
    #pragma unroll
    for (int g = 0; g < 8; g++) vr[g] = vs[g][tid];
    float* og = ao + (size_t)tok * HS_DIM;
    #pragma unroll
    for (int h = 0; h < N_HEADS; h++) {
        float a = 0.f;
        #pragma unroll
        for (int g = 0; g < 8; g++) a += w[h][g] * vr[g];
        og[h * HEAD_D + tid] = a;
    }
}

// ---------------------------------------------------------------------------
extern "C" void kernel_launch(void* const* d_in, const int* in_sizes, int n_in,
                              void* d_out, int out_size)
{
    const float* x  = (const float*)d_in[0];  // hidden_states [2,4096,4096]
    const float* Wq = (const float*)d_in[1];  // [4096,4096]
    const float* Wk = (const float*)d_in[2];  // [4096,1024]
    const float* Wv = (const float*)d_in[3];  // [4096,1024]
    const float* Wo = (const float*)d_in[4];  // [4096,4096]
    float* out = (float*)d_out;               // [2,4096,4096]

    float *q, *k, *v, *ao;
    cudaGetSymbolAddress((void**)&q,  g_q);
    cudaGetSymbolAddress((void**)&k,  g_k);
    cudaGetSymbolAddress((void**)&v,  g_v);
    cudaGetSymbolAddress((void**)&ao, g_ao);

    dim3 blk(256);
    // q/k/v projections
    sgemm_kernel<<<dim3(HS_DIM  / 128, M_TOK / 128), blk>>>(x, Wq, q, M_TOK, HS_DIM,  HS_DIM);
    sgemm_kernel<<<dim3(KVD_DIM / 128, M_TOK / 128), blk>>>(x, Wk, k, M_TOK, KVD_DIM, HS_DIM);
    sgemm_kernel<<<dim3(KVD_DIM / 128, M_TOK / 128), blk>>>(x, Wv, v, M_TOK, KVD_DIM, HS_DIM);
    // per-token head attention (RoPE elided: exact rotation invariance)
    attn_kernel<<<M_TOK, 128>>>(q, k, v, ao);
    // output projection
    sgemm_kernel<<<dim3(HS_DIM / 128, M_TOK / 128), blk>>>(ao, Wo, out, M_TOK, HS_DIM, HS_DIM);
}

// round 4
// speedup vs baseline: 6.5363x; 6.5363x over previous
#include <cuda_runtime.h>
#include <cuda_fp16.h>
#include <cstdint>

// Problem: B=2, S=4096, HS=4096, H=32, KV=8, D=128 -> M = 8192
#define M_TOK   8192
#define HS_DIM  4096
#define KVD_DIM 1024
#define N_HEADS 32
#define N_KV    8
#define HEAD_D  128

// GEMM tiling (fp16 mma.sync, fp32 accum)
#define BM 128
#define BN 128
#define BK 64            // 64 halfs = 128 B rows (SW128-style swizzle)
#define STAGES 4
#define GT 256           // 8 warps: 2 (m) x 4 (n), warp tile 64x32
#define STAGE_BYTES 16384
#define SMEM_BYTES (STAGES * 2 * STAGE_BYTES + 256)

// Scratch (__device__ globals: allocation-free per harness rules)
__device__ float  g_q  [(size_t)M_TOK * HS_DIM];
__device__ float  g_k  [(size_t)M_TOK * KVD_DIM];
__device__ float  g_v  [(size_t)M_TOK * KVD_DIM];
__device__ __align__(16) __half g_xh  [(size_t)M_TOK * HS_DIM];
__device__ __align__(16) __half g_aoh [(size_t)M_TOK * HS_DIM];
__device__ __align__(16) __half g_WqTh[(size_t)HS_DIM * HS_DIM];    // [N,K] K-major
__device__ __align__(16) __half g_WkTh[(size_t)KVD_DIM * HS_DIM];
__device__ __align__(16) __half g_WvTh[(size_t)KVD_DIM * HS_DIM];
__device__ __align__(16) __half g_WoTh[(size_t)HS_DIM * HS_DIM];

// ---------------------------------------------------------------------------
// PTX helpers (sm_80-era only: valid on plain sm_103 target)
// ---------------------------------------------------------------------------
__device__ __forceinline__ uint32_t smem_u32(const void* p) {
    uint32_t a;
    asm("{ .reg .u64 t; cvta.to.shared.u64 t, %1; cvt.u32.u64 %0, t; }" : "=r"(a) : "l"(p));
    return a;
}
#define CP_ASYNC16(smem, gptr) \
    asm volatile("cp.async.cg.shared.global [%0], [%1], 16;\n" :: "r"(smem), "l"(gptr))
#define CP_COMMIT() asm volatile("cp.async.commit_group;\n" ::: "memory")
#define CP_WAIT(n)  asm volatile("cp.async.wait_group %0;\n" :: "n"(n) : "memory")

#define LDSM_X4(r, addr) \
    asm volatile("ldmatrix.sync.aligned.m8n8.x4.shared.b16 {%0,%1,%2,%3}, [%4];" \
        : "=r"((r)[0]), "=r"((r)[1]), "=r"((r)[2]), "=r"((r)[3]) : "r"(addr))

#define MMA16816(d, a, b0, b1) \
    asm volatile("mma.sync.aligned.m16n8k16.row.col.f32.f16.f16.f32 " \
        "{%0,%1,%2,%3}, {%4,%5,%6,%7}, {%8,%9}, {%0,%1,%2,%3};" \
        : "+f"((d)[0]), "+f"((d)[1]), "+f"((d)[2]), "+f"((d)[3]) \
        : "r"((a)[0]), "r"((a)[1]), "r"((a)[2]), "r"((a)[3]), "r"(b0), "r"(b1))

// ---------------------------------------------------------------------------
// fp16 GEMM: C[M,N](f32) = A[M,K](f16, row-major) @ Bt[N,K](f16, K-major)^T
// Grid (N/BN, M/BM), 256 threads, 4-stage cp.async pipeline, ldmatrix + mma.
// ---------------------------------------------------------------------------
__global__ __launch_bounds__(GT, 1)
void gemm_f16(const __half* __restrict__ A, const __half* __restrict__ Bt,
              float* __restrict__ C, int K, int N)
{
    extern __shared__ char smem_raw[];
    const uint32_t base = (smem_u32(smem_raw) + 127u) & ~127u;
    const uint32_t sA = base;
    const uint32_t sB = base + STAGES * STAGE_BYTES;

    const int tid  = threadIdx.x;
    const int wid  = tid >> 5, lane = tid & 31;
    const int mtile = blockIdx.y, ntile = blockIdx.x;
    const int warp_m = wid & 1;        // 2 m-warps   (64 rows each)
    const int warp_n = wid >> 1;       // 4 n-warps   (32 cols each)

    const __half* Ag = A  + (size_t)(mtile * BM) * K;
    const __half* Bg = Bt + (size_t)(ntile * BN) * K;

    float acc[4][4][4];
    #pragma unroll
    for (int i = 0; i < 4; i++)
        #pragma unroll
        for (int j = 0; j < 4; j++)
            #pragma unroll
            for (int r = 0; r < 4; r++) acc[i][j][r] = 0.f;

    // Stage loader: 1024 16B chunks each for A and B; 128B rows, XOR-16B swizzle.
    auto load_stage = [&](int s, int k0) {
        uint32_t a0 = sA + s * STAGE_BYTES, b0 = sB + s * STAGE_BYTES;
        #pragma unroll
        for (int j = 0; j < 4; j++) {
            int c = tid + j * 256;
            int r = c >> 3, c16 = c & 7;
            uint32_t so = a0 + ((r * 128 + c16 * 16) ^ ((r & 7) << 4));
            CP_ASYNC16(so, Ag + (size_t)r * K + k0 + c16 * 8);
        }
        #pragma unroll
        for (int j = 0; j < 4; j++) {
            int c = tid + j * 256;
            int r = c >> 3, c16 = c & 7;
            uint32_t so = b0 + ((r * 128 + c16 * 16) ^ ((r & 7) << 4));
            CP_ASYNC16(so, Bg + (size_t)r * K + k0 + c16 * 8);
        }
        CP_COMMIT();
    };

    const int NIT = K / BK;            // 64
    load_stage(0, 0); load_stage(1, BK); load_stage(2, 2 * BK);

    for (int i = 0; i < NIT; i++) {
        const int s = i & 3;
        CP_WAIT(2);                    // stage i landed
        __syncthreads();               // also protects buffer (i+3)&3 for reuse
        if (i + 3 < NIT) load_stage((i + 3) & 3, (i + 3) * BK);

        const uint32_t aB = sA + s * STAGE_BYTES;
        const uint32_t bB = sB + s * STAGE_BYTES;
        #pragma unroll
        for (int ks = 0; ks < 4; ks++) {
            const int kbyte = ks * 32;                    // k16 = 32 bytes
            uint32_t a[4][4], bb[2][4];
            #pragma unroll
            for (int ii = 0; ii < 4; ii++) {              // A m-tiles (16 rows each)
                int row = warp_m * 64 + ii * 16 + (lane & 15);
                uint32_t ad = aB + ((row * 128 + kbyte + ((lane >> 4) << 4)) ^ ((row & 7) << 4));
                LDSM_X4(a[ii], ad);
            }
            #pragma unroll
            for (int jj = 0; jj < 2; jj++) {              // B: 2 x (n16,k16)
                int row = warp_n * 32 + jj * 16 + (lane & 15);
                uint32_t bd = bB + ((row * 128 + kbyte + ((lane >> 4) << 4)) ^ ((row & 7) << 4));
                LDSM_X4(bb[jj], bd);
            }
            #pragma unroll
            for (int ii = 0; ii < 4; ii++)
                #pragma unroll
                for (int j = 0; j < 4; j++)
                    MMA16816(acc[ii][j], a[ii], bb[j >> 1][j & 1], bb[j >> 1][2 + (j & 1)]);
        }
    }

    // Epilogue
    float* Cp = C + (size_t)(mtile * BM) * N + ntile * BN;
    #pragma unroll
    for (int ii = 0; ii < 4; ii++)
        #pragma unroll
        for (int j = 0; j < 4; j++) {
            int r0 = warp_m * 64 + ii * 16 + (lane >> 2);
            int c0 = warp_n * 32 + j * 8 + (lane & 3) * 2;
            float2 v0 = { acc[ii][j][0], acc[ii][j][1] };
            float2 v1 = { acc[ii][j][2], acc[ii][j][3] };
            *(float2*)(Cp + (size_t)r0 * N + c0)       = v0;
            *(float2*)(Cp + (size_t)(r0 + 8) * N + c0) = v1;
        }
}

// ---------------------------------------------------------------------------
// Elementwise fp32 -> fp16 (rn). n multiple of 1024; 4 elems/thread.
// ---------------------------------------------------------------------------
__global__ __launch_bounds__(256)
void f32_to_f16(const float* __restrict__ in, __half* __restrict__ out)
{
    size_t i = (size_t)blockIdx.x * blockDim.x + threadIdx.x;
    float4 v = ((const float4*)in)[i];
    __half2* o = (__half2*)out;
    o[2 * i + 0] = __floats2half2_rn(v.x, v.y);
    o[2 * i + 1] = __floats2half2_rn(v.z, v.w);
}

// ---------------------------------------------------------------------------
// Transpose [R,C] f32 -> [C,R] f16 (rn)
// ---------------------------------------------------------------------------
__global__ __launch_bounds__(256)
void transpose_f16(const float* __restrict__ in, __half* __restrict__ out, int R, int C)
{
    __shared__ float t[32][33];
    const int tx = threadIdx.x, ty = threadIdx.y;     // 32 x 8
    const int bx = blockIdx.x * 32, by = blockIdx.y * 32;
    #pragma unroll
    for (int r = 0; r < 32; r += 8)
        t[ty + r][tx] = in[(size_t)(by + ty + r) * C + bx + tx];
    __syncthreads();
    #pragma unroll
    for (int r = 0; r < 32; r += 8)
        out[(size_t)(bx + ty + r) * R + by + tx] = __float2half_rn(t[tx][ty + r]);
}

// ---------------------------------------------------------------------------
// Per-token attention (RoPE cancels exactly in q.k; GQA repeat collapses).
// Writes ao directly as fp16 (feeds the output GEMM).
// ---------------------------------------------------------------------------
__global__ __launch_bounds__(128)
void attn_kernel(const float* __restrict__ q, const float* __restrict__ k,
                 const float* __restrict__ v, __half* __restrict__ ao)
{
    const int tok = blockIdx.x;
    const int tid = threadIdx.x;

    __shared__ float qs[N_HEADS][132];
    __shared__ float ks[N_KV][132];
    __shared__ float vs[N_KV][132];
    __shared__ float sc[N_HEADS][8];
    __shared__ float w [N_HEADS][8];

    const float* qg = q + (size_t)tok * HS_DIM;
    const float* kg = k + (size_t)tok * KVD_DIM;
    const float* vg = v + (size_t)tok * KVD_DIM;

    for (int i = tid; i < HS_DIM / 4; i += 128) {
        float4 t4 = *(const float4*)(qg + i * 4);
        int h = (i * 4) >> 7, d = (i * 4) & 127;
        *(float4*)&qs[h][d] = t4;
    }
    for (int i = tid; i < KVD_DIM / 4; i += 128) {
        float4 t4 = *(const float4*)(kg + i * 4);
        int g = (i * 4) >> 7, d = (i * 4) & 127;
        *(float4*)&ks[g][d] = t4;
    }
    for (int i = tid; i < KVD_DIM / 4; i += 128) {
        float4 t4 = *(const float4*)(vg + i * 4);
        int g = (i * 4) >> 7, d = (i * 4) & 127;
        *(float4*)&vs[g][d] = t4;
    }
    __syncthreads();

    const float scale = 0.088388347648318447f;   // 1/sqrt(128)
    #pragma unroll
    for (int r = 0; r < 2; r++) {
        int sid = r * 128 + tid;
        int h = sid >> 3, g = sid & 7;
        float a = 0.f;
        #pragma unroll 8
        for (int d = 0; d < HEAD_D; d++) a += qs[h][d] * ks[g][d];
        sc[h][g] = a * scale;
    }
    __syncthreads();

    if (tid < N_HEADS) {
        float m = sc[tid][0];
        #pragma unroll
        for (int g = 1; g < 8; g++) m = fmaxf(m, sc[tid][g]);
        float e[8], s = 0.f;
        #pragma unroll
        for (int g = 0; g < 8; g++) { e[g] = __expf(sc[tid][g] - m); s += e[g]; }
        float inv = 1.f / s;
        #pragma unroll
        for (int g = 0; g < 8; g++) w[tid][g] = e[g] * inv;
    }
    __syncthreads();

    float vr[8];
    #pragma unroll
    for (int g = 0; g < 8; g++) vr[g] = vs[g][tid];
    __half* og = ao + (size_t)tok * HS_DIM;
    #pragma unroll
    for (int h = 0; h < N_HEADS; h++) {
        float a = 0.f;
        #pragma unroll
        for (int g = 0; g < 8; g++) a += w[h][g] * vr[g];
        og[h * HEAD_D + tid] = __float2half_rn(a);
    }
}

// ---------------------------------------------------------------------------
extern "C" void kernel_launch(void* const* d_in, const int* in_sizes, int n_in,
                              void* d_out, int out_size)
{
    const float* x  = (const float*)d_in[0];
    const float* Wq = (const float*)d_in[1];
    const float* Wk = (const float*)d_in[2];
    const float* Wv = (const float*)d_in[3];
    const float* Wo = (const float*)d_in[4];
    float* out = (float*)d_out;

    float *q, *k, *v;
    __half *xh, *aoh, *WqTh, *WkTh, *WvTh, *WoTh;
    cudaGetSymbolAddress((void**)&q,    g_q);
    cudaGetSymbolAddress((void**)&k,    g_k);
    cudaGetSymbolAddress((void**)&v,    g_v);
    cudaGetSymbolAddress((void**)&xh,   g_xh);
    cudaGetSymbolAddress((void**)&aoh,  g_aoh);
    cudaGetSymbolAddress((void**)&WqTh, g_WqTh);
    cudaGetSymbolAddress((void**)&WkTh, g_WkTh);
    cudaGetSymbolAddress((void**)&WvTh, g_WvTh);
    cudaGetSymbolAddress((void**)&WoTh, g_WoTh);

    cudaFuncSetAttribute(gemm_f16, cudaFuncAttributeMaxDynamicSharedMemorySize, SMEM_BYTES);

    // fp32 -> fp16 input + weight prep
    f32_to_f16<<<(size_t)M_TOK * HS_DIM / 1024, 256>>>(x, xh);
    dim3 tb(32, 8);
    transpose_f16<<<dim3(HS_DIM  / 32, HS_DIM / 32), tb>>>(Wq, WqTh, HS_DIM, HS_DIM);
    transpose_f16<<<dim3(KVD_DIM / 32, HS_DIM / 32), tb>>>(Wk, WkTh, HS_DIM, KVD_DIM);
    transpose_f16<<<dim3(KVD_DIM / 32, HS_DIM / 32), tb>>>(Wv, WvTh, HS_DIM, KVD_DIM);
    transpose_f16<<<dim3(HS_DIM  / 32, HS_DIM / 32), tb>>>(Wo, WoTh, HS_DIM, HS_DIM);

    // Projections (tensor cores via mma.sync)
    gemm_f16<<<dim3(HS_DIM  / BN, M_TOK / BM), GT, SMEM_BYTES>>>(xh, WqTh, q, HS_DIM, HS_DIM);
    gemm_f16<<<dim3(KVD_DIM / BN, M_TOK / BM), GT, SMEM_BYTES>>>(xh, WkTh, k, HS_DIM, KVD_DIM);
    gemm_f16<<<dim3(KVD_DIM / BN, M_TOK / BM), GT, SMEM_BYTES>>>(xh, WvTh, v, HS_DIM, KVD_DIM);

    // Per-token head attention (fp32 in, fp16 out)
    attn_kernel<<<M_TOK, 128>>>(q, k, v, aoh);

    // Output projection
    gemm_f16<<<dim3(HS_DIM / BN, M_TOK / BM), GT, SMEM_BYTES>>>(aoh, WoTh, out, HS_DIM, HS_DIM);
}